// round 6
// baseline (speedup 1.0000x reference)
#include <cuda_runtime.h>

// ---------------- problem-size constants ----------------
#define NMAX 50000
#define EMAX 800000
#define F1   64
#define F2   32
#define DIN  128
#define DOUT 128

// ---------------- device scratch ----------------
__device__ int   g_cnt[NMAX];
__device__ int   g_rowptr[NMAX + 1];
__device__ int   g_pos[NMAX];
__device__ float g_dinv[NMAX];
__device__ int2  g_edge[EMAX];
__device__ float g_h1[NMAX * F1];
__device__ float g_a1[NMAX * F1];
__device__ float g_h2[NMAX * F2];
__device__ float g_a2[NMAX * F2];
__device__ int   g_is64;
__device__ int   g_bsum[128];
__device__ int   g_barrier[8];

// ---------------- software grid barrier (persistent kernel) ----------------
// Counters are zeroed by reset_barrier_kernel BEFORE this kernel each replay,
// so plain count-up to gridDim.x is deadlock-free (no stale spinners possible
// across the kernel boundary).
__device__ __forceinline__ void grid_sync(int idx) {
    __syncthreads();
    if (threadIdx.x == 0) {
        __threadfence();
        atomicAdd(&g_barrier[idx], 1);
        while (atomicAdd(&g_barrier[idx], 0) < (int)gridDim.x) __nanosleep(20);
    }
    __syncthreads();
}

__global__ void reset_barrier_kernel() {
    if (threadIdx.x < 8) g_barrier[threadIdx.x] = 0;
}

// ---------------- fused persistent CSR-build kernel ----------------
// grid = ceil(n/512) blocks (<=148, all resident), 256 threads.
// phases: zero+detect | count | chunk-reduce | scan->rowptr/pos/dinv | scatter
__global__ void __launch_bounds__(256)
prep_kernel(const int* __restrict__ w, int E, int n)
{
    const int tid  = threadIdx.x;
    const int bid  = blockIdx.x;
    const int lane = tid & 31;
    const int wid  = tid >> 5;
    const int gsz  = gridDim.x * 256;
    const int gtid = bid * 256 + tid;

    __shared__ int ws[8];
    __shared__ int s_boff;

    // ---- phase 0: zero counters; block 0 detects edge dtype
    for (int i = gtid; i < n; i += gsz) g_cnt[i] = 0;
    if (bid == 0) {
        __shared__ int any_nonzero;
        if (tid == 0) any_nonzero = 0;
        __syncthreads();
        int stride = (2 * E) / 512;
        int idx = 2 * (tid * stride) + 1;
        if (w[idx] != 0) atomicOr(&any_nonzero, 1);
        __syncthreads();
        if (tid == 0) g_is64 = any_nonzero ? 0 : 1;
    }
    grid_sync(0);

    const int is64 = __ldcg(&g_is64);

    // ---- phase 1: degree count
    for (int e = gtid; e < E; e += gsz) {
        int d = is64 ? w[2 * (E + e)] : w[E + e];
        atomicAdd(&g_cnt[d], 1);
    }
    grid_sync(1);

    // ---- phase 2: per-block chunk reduce (chunk = 512 nodes, 2/thread)
    const int base = bid * 512 + tid * 2;
    const int a0 = (base     < n) ? __ldcg(&g_cnt[base])     : 0;
    const int a1 = (base + 1 < n) ? __ldcg(&g_cnt[base + 1]) : 0;
    const int tsum = a0 + a1;
    {
        int s = tsum;
#pragma unroll
        for (int o = 16; o; o >>= 1) s += __shfl_down_sync(0xffffffffu, s, o);
        if (lane == 0) ws[wid] = s;
        __syncthreads();
        if (tid < 8) {
            int t = ws[tid];
#pragma unroll
            for (int o = 4; o; o >>= 1) t += __shfl_down_sync(0xffu, t, o);
            if (tid == 0) g_bsum[bid] = t;
        }
        __syncthreads();            // ws reused below
    }
    grid_sync(2);

    // ---- phase 3: global offset + local exclusive scan -> rowptr/pos/dinv
    {
        // warp-inclusive scan of per-thread sums
        int x = tsum;
#pragma unroll
        for (int o = 1; o < 32; o <<= 1) {
            int y = __shfl_up_sync(0xffffffffu, x, o);
            if (lane >= o) x += y;
        }
        const int wex = x - tsum;
        if (lane == 31) ws[wid] = x;

        // warp 0 additionally sums block sums below bid
        if (tid < 32) {
            int s = 0;
            for (int i = tid; i < bid; i += 32) s += __ldcg(&g_bsum[i]);
#pragma unroll
            for (int o = 16; o; o >>= 1) s += __shfl_down_sync(0xffffffffu, s, o);
            if (tid == 0) s_boff = s;
        }
        __syncthreads();
        if (tid < 8) {
            int orig = ws[tid];
            int t = orig;
#pragma unroll
            for (int o = 1; o < 8; o <<= 1) {
                int y = __shfl_up_sync(0xffu, t, o);
                if (tid >= o) t += y;
            }
            ws[tid] = t - orig;
        }
        __syncthreads();

        int run = s_boff + ws[wid] + wex;
        if (base < n) {
            g_rowptr[base] = run;
            g_pos[base] = run;
            g_dinv[base] = rsqrtf((float)(a0 + 1));
        }
        run += a0;
        if (base + 1 < n) {
            g_rowptr[base + 1] = run;
            g_pos[base + 1] = run;
            g_dinv[base + 1] = rsqrtf((float)(a1 + 1));
        }
        if (bid == 0 && tid == 0) g_rowptr[n] = E;
    }
    grid_sync(3);

    // ---- phase 4: scatter edges into CSR slots with normalized weights
    for (int e = gtid; e < E; e += gsz) {
        int s, d;
        if (is64) { s = w[2 * e]; d = w[2 * (E + e)]; }
        else      { s = w[e];     d = w[E + e];       }
        float wn = __ldcg(&g_dinv[s]) * __ldcg(&g_dinv[d]);
        int p = atomicAdd(&g_pos[d], 1);
        g_edge[p] = make_int2(s, __float_as_int(wn));
    }
}

// ---------------- register-tiled GEMM (proven round-3 version) ----------------
template<int KIN, int KOUT, int TN, bool INACT, bool OBIAS>
__global__ void __launch_bounds__((TN / 4) * 16)
gemm_rt(const float* __restrict__ A, const float* __restrict__ W,
        const float* __restrict__ ib, const float* __restrict__ ob,
        float* __restrict__ H, int n)
{
    constexpr int TM = 64;
    constexpr int TK = (KIN < 32) ? KIN : 32;
    constexpr int NTX = TN / 4;
    constexpr int NTH = NTX * 16;
    constexpr int XPITCH = TM + 4;

    __shared__ float Xs[TK * XPITCH];
    __shared__ float Ws[TK * TN];

    const int tid = threadIdx.x;
    const int tx = tid % NTX;
    const int ty = tid / NTX;
    const int nb = blockIdx.x * TM;
    const int jn = blockIdx.y * TN;
    const int valid = min(TM, n - nb);

    float acc[4][4];
#pragma unroll
    for (int i = 0; i < 4; i++)
#pragma unroll
        for (int j = 0; j < 4; j++) acc[i][j] = 0.0f;

    for (int kt = 0; kt < KIN; kt += TK) {
#pragma unroll
        for (int idx = tid; idx < TM * TK / 4; idx += NTH) {
            int r  = idx / (TK / 4);
            int kq = idx % (TK / 4);
            float4 v = make_float4(0.f, 0.f, 0.f, 0.f);
            if (r < valid)
                v = *reinterpret_cast<const float4*>(
                        A + (long long)(nb + r) * KIN + kt + kq * 4);
            if (INACT) {
                const float4 bb = *reinterpret_cast<const float4*>(ib + kt + kq * 4);
                v.x = fmaxf(v.x + bb.x, 0.f);
                v.y = fmaxf(v.y + bb.y, 0.f);
                v.z = fmaxf(v.z + bb.z, 0.f);
                v.w = fmaxf(v.w + bb.w, 0.f);
            }
            Xs[(kq * 4 + 0) * XPITCH + r] = v.x;
            Xs[(kq * 4 + 1) * XPITCH + r] = v.y;
            Xs[(kq * 4 + 2) * XPITCH + r] = v.z;
            Xs[(kq * 4 + 3) * XPITCH + r] = v.w;
        }
#pragma unroll
        for (int idx = tid; idx < TK * TN / 4; idx += NTH) {
            int kk = idx / (TN / 4);
            int jq = idx % (TN / 4);
            *reinterpret_cast<float4*>(Ws + kk * TN + jq * 4) =
                *reinterpret_cast<const float4*>(
                    W + (long long)(kt + kk) * KOUT + jn + jq * 4);
        }
        __syncthreads();

#pragma unroll
        for (int kk = 0; kk < TK; kk++) {
            const float4 a = *reinterpret_cast<const float4*>(Xs + kk * XPITCH + ty * 4);
            const float4 b = *reinterpret_cast<const float4*>(Ws + kk * TN + tx * 4);
            acc[0][0] += a.x * b.x; acc[0][1] += a.x * b.y; acc[0][2] += a.x * b.z; acc[0][3] += a.x * b.w;
            acc[1][0] += a.y * b.x; acc[1][1] += a.y * b.y; acc[1][2] += a.y * b.z; acc[1][3] += a.y * b.w;
            acc[2][0] += a.z * b.x; acc[2][1] += a.z * b.y; acc[2][2] += a.z * b.z; acc[2][3] += a.z * b.w;
            acc[3][0] += a.w * b.x; acc[3][1] += a.w * b.y; acc[3][2] += a.w * b.z; acc[3][3] += a.w * b.w;
        }
        __syncthreads();
    }

    float4 bo = make_float4(0.f, 0.f, 0.f, 0.f);
    if (OBIAS) bo = *reinterpret_cast<const float4*>(ob + jn + tx * 4);
#pragma unroll
    for (int i = 0; i < 4; i++) {
        int node = nb + ty * 4 + i;
        if (node < n) {
            float4 v = make_float4(acc[i][0] + bo.x, acc[i][1] + bo.y,
                                   acc[i][2] + bo.z, acc[i][3] + bo.w);
            *reinterpret_cast<float4*>(H + (long long)node * KOUT + jn + tx * 4) = v;
        }
    }
}

// ---------------- CSR gather propagation ----------------
__global__ void __launch_bounds__(256)
prop64_kernel(const float* __restrict__ h, float* __restrict__ g, int n)
{
    const int v = (blockIdx.x * blockDim.x + threadIdx.x) >> 5;
    if (v >= n) return;
    const int lane = threadIdx.x & 31;
    const int r0 = g_rowptr[v];
    const int r1 = g_rowptr[v + 1];
    const float di = g_dinv[v];

    float2 acc = *reinterpret_cast<const float2*>(h + (long long)v * F1 + lane * 2);
    acc.x *= di * di;
    acc.y *= di * di;

    int j = r0;
    const int nfull = r0 + ((r1 - r0) & ~3);
    for (; j < nfull; j += 4) {
        int2 e0 = g_edge[j], e1 = g_edge[j + 1], e2 = g_edge[j + 2], e3 = g_edge[j + 3];
        float2 v0 = *reinterpret_cast<const float2*>(h + (long long)e0.x * F1 + lane * 2);
        float2 v1 = *reinterpret_cast<const float2*>(h + (long long)e1.x * F1 + lane * 2);
        float2 v2 = *reinterpret_cast<const float2*>(h + (long long)e2.x * F1 + lane * 2);
        float2 v3 = *reinterpret_cast<const float2*>(h + (long long)e3.x * F1 + lane * 2);
        float w0 = __int_as_float(e0.y), w1 = __int_as_float(e1.y);
        float w2 = __int_as_float(e2.y), w3 = __int_as_float(e3.y);
        acc.x += w0 * v0.x; acc.y += w0 * v0.y;
        acc.x += w1 * v1.x; acc.y += w1 * v1.y;
        acc.x += w2 * v2.x; acc.y += w2 * v2.y;
        acc.x += w3 * v3.x; acc.y += w3 * v3.y;
    }
    for (; j < r1; j++) {
        int2 e = g_edge[j];
        float2 vv = *reinterpret_cast<const float2*>(h + (long long)e.x * F1 + lane * 2);
        float w = __int_as_float(e.y);
        acc.x += w * vv.x; acc.y += w * vv.y;
    }
    *reinterpret_cast<float2*>(g + (long long)v * F1 + lane * 2) = acc;
}

__global__ void __launch_bounds__(256)
prop32_kernel(const float* __restrict__ h, float* __restrict__ g, int n)
{
    const int v = (blockIdx.x * blockDim.x + threadIdx.x) >> 5;
    if (v >= n) return;
    const int lane = threadIdx.x & 31;
    const int r0 = g_rowptr[v];
    const int r1 = g_rowptr[v + 1];
    const float di = g_dinv[v];

    float acc = di * di * h[(long long)v * F2 + lane];

    int j = r0;
    const int nfull = r0 + ((r1 - r0) & ~3);
    for (; j < nfull; j += 4) {
        int2 e0 = g_edge[j], e1 = g_edge[j + 1], e2 = g_edge[j + 2], e3 = g_edge[j + 3];
        float v0 = h[(long long)e0.x * F2 + lane];
        float v1 = h[(long long)e1.x * F2 + lane];
        float v2 = h[(long long)e2.x * F2 + lane];
        float v3 = h[(long long)e3.x * F2 + lane];
        acc += __int_as_float(e0.y) * v0;
        acc += __int_as_float(e1.y) * v1;
        acc += __int_as_float(e2.y) * v2;
        acc += __int_as_float(e3.y) * v3;
    }
    for (; j < r1; j++) {
        int2 e = g_edge[j];
        acc += __int_as_float(e.y) * h[(long long)e.x * F2 + lane];
    }
    g[(long long)v * F2 + lane] = acc;
}

// ---------------- launcher (forked-stream capture) ----------------
extern "C" void kernel_launch(void* const* d_in, const int* in_sizes, int n_in,
                              void* d_out, int out_size)
{
    const float* x  = (const float*)d_in[0];
    const int*   ei = (const int*)  d_in[1];
    const float* W1 = (const float*)d_in[2];
    const float* b1 = (const float*)d_in[3];
    const float* W2 = (const float*)d_in[4];
    const float* b2 = (const float*)d_in[5];
    const float* Wl = (const float*)d_in[6];
    const float* bl = (const float*)d_in[7];
    float* out = (float*)d_out;

    const int n = in_sizes[0] / DIN;
    const int E = in_sizes[1] / 2;

    void *ph1, *pa1, *ph2, *pa2;
    cudaGetSymbolAddress(&ph1, g_h1);
    cudaGetSymbolAddress(&pa1, g_a1);
    cudaGetSymbolAddress(&ph2, g_h2);
    cudaGetSymbolAddress(&pa2, g_a2);
    float* h1 = (float*)ph1; float* a1 = (float*)pa1;
    float* h2 = (float*)ph2; float* a2 = (float*)pa2;

    const int nbp  = (n + 511) / 512;        // persistent prep blocks (98 <= 148)
    const int nblk = (n + 63) / 64;
    const int pblk = (n * 32 + 255) / 256;

    // side stream + fork/join events (host objects only; no device memory)
    cudaStream_t s2;
    cudaStreamCreateWithFlags(&s2, cudaStreamNonBlocking);
    cudaEvent_t evFork, evJoin;
    cudaEventCreateWithFlags(&evFork, cudaEventDisableTiming);
    cudaEventCreateWithFlags(&evJoin, cudaEventDisableTiming);

    // fork: CSR build on s2, concurrent with gemm1 on the main stream
    cudaEventRecord(evFork, 0);
    cudaStreamWaitEvent(s2, evFork, 0);

    reset_barrier_kernel<<<1, 32, 0, s2>>>();
    prep_kernel<<<nbp, 256, 0, s2>>>(ei, E, n);
    cudaEventRecord(evJoin, s2);

    // main stream: layer-1 GEMM overlaps CSR build
    gemm_rt<DIN, F1, 64, false, false><<<dim3(nblk, 1), 256>>>(x, W1, nullptr, nullptr, h1, n);

    // join: propagation needs both gemm1 and CSR
    cudaStreamWaitEvent(0, evJoin, 0);

    prop64_kernel<<<pblk, 256>>>(h1, a1, n);
    gemm_rt<F1, F2, 32, true, false><<<dim3(nblk, 1), 128>>>(a1, W2, b1, nullptr, h2, n);
    prop32_kernel<<<pblk, 256>>>(h2, a2, n);
    gemm_rt<F2, DOUT, 64, true, true><<<dim3(nblk, 2), 256>>>(a2, Wl, b2, bl, out, n);

    cudaEventDestroy(evFork);
    cudaEventDestroy(evJoin);
    cudaStreamDestroy(s2);
}

// round 7
// speedup vs baseline: 1.1214x; 1.1214x over previous
#include <cuda_runtime.h>

// ---------------- problem-size constants ----------------
#define NMAX 50000
#define EMAX 800000
#define F1   64
#define F2   32
#define DIN  128
#define DOUT 128

#define SCAN_ELEM 1024

// ---------------- device scratch ----------------
__device__ int   g_cnt[NMAX];
__device__ int   g_rowptr[NMAX + 1];
__device__ int   g_pos[NMAX];
__device__ float g_dinv[NMAX];
__device__ int2  g_edge[EMAX];
__device__ float g_h1[NMAX * F1];
__device__ float g_a1[NMAX * F1];
__device__ float g_h2[NMAX * F2];
__device__ float g_a2[NMAX * F2];
__device__ int   g_is64;
__device__ int   g_bsum[64];

// ---------------- detect dtype + zero counters (merged) ----------------
__global__ void detect_zero_kernel(const int* __restrict__ w, int E, int n) {
    int i = blockIdx.x * blockDim.x + threadIdx.x;
    if (i < n) g_cnt[i] = 0;
    if (blockIdx.x == 0) {
        __shared__ int any_nonzero;
        if (threadIdx.x == 0) any_nonzero = 0;
        __syncthreads();
        int stride = (2 * E) / 512;
        int idx = 2 * (threadIdx.x * stride) + 1;
        if (w[idx] != 0) atomicOr(&any_nonzero, 1);
        __syncthreads();
        if (threadIdx.x == 0) g_is64 = any_nonzero ? 0 : 1;
    }
}

__global__ void count_kernel(const int* __restrict__ w, int E) {
    int e = blockIdx.x * blockDim.x + threadIdx.x;
    if (e >= E) return;
    int d = g_is64 ? w[2 * (E + e)] : w[E + e];
    atomicAdd(&g_cnt[d], 1);
}

// ---- scan phase 1: per-block reduce (1024 elems/block)
__global__ void scan1_kernel(int n) {
    const int tid = threadIdx.x;
    const int base = blockIdx.x * SCAN_ELEM + tid * 4;
    int s = 0;
#pragma unroll
    for (int i = 0; i < 4; i++) {
        int idx = base + i;
        if (idx < n) s += g_cnt[idx];
    }
#pragma unroll
    for (int o = 16; o; o >>= 1) s += __shfl_down_sync(0xffffffffu, s, o);
    __shared__ int ws[8];
    if ((tid & 31) == 0) ws[tid >> 5] = s;
    __syncthreads();
    if (tid < 8) {
        int t = ws[tid];
#pragma unroll
        for (int o = 4; o; o >>= 1) t += __shfl_down_sync(0xffu, t, o);
        if (tid == 0) g_bsum[blockIdx.x] = t;
    }
}

// ---- scan phase 2+3 fused: each block scans the <=64 block sums itself,
//      then does its local scan -> rowptr / pos / dinv
__global__ void scan3_kernel(int n, int E, int nblk) {
    const int tid = threadIdx.x;
    const int lane = tid & 31;
    const int wid = tid >> 5;
    const int base = blockIdx.x * SCAN_ELEM + tid * 4;

    __shared__ int s_boff;
    if (tid < 32) {
        int a0 = (tid < nblk) ? g_bsum[tid] : 0;
        int a1 = (tid + 32 < nblk) ? g_bsum[tid + 32] : 0;
        int x0 = a0, x1 = a1;
#pragma unroll
        for (int o = 1; o < 32; o <<= 1) {
            int y0 = __shfl_up_sync(0xffffffffu, x0, o);
            int y1 = __shfl_up_sync(0xffffffffu, x1, o);
            if (lane >= o) { x0 += y0; x1 += y1; }
        }
        int tot0 = __shfl_sync(0xffffffffu, x0, 31);
        int b = blockIdx.x;
        int incl, own;
        if (b < 32) {
            incl = __shfl_sync(0xffffffffu, x0, b);
            own  = __shfl_sync(0xffffffffu, a0, b);
        } else {
            incl = tot0 + __shfl_sync(0xffffffffu, x1, b - 32);
            own  = __shfl_sync(0xffffffffu, a1, b - 32);
        }
        if (tid == 0) s_boff = incl - own;
    }

    int a[4];
    int tsum = 0;
#pragma unroll
    for (int i = 0; i < 4; i++) {
        int idx = base + i;
        a[i] = (idx < n) ? g_cnt[idx] : 0;
        tsum += a[i];
    }
    int x = tsum;
#pragma unroll
    for (int o = 1; o < 32; o <<= 1) {
        int y = __shfl_up_sync(0xffffffffu, x, o);
        if (lane >= o) x += y;
    }
    const int wex = x - tsum;

    __shared__ int ws[8];
    if (lane == 31) ws[wid] = x;
    __syncthreads();
    if (tid < 8) {
        int orig = ws[tid];
        int t = orig;
#pragma unroll
        for (int o = 1; o < 8; o <<= 1) {
            int y = __shfl_up_sync(0xffu, t, o);
            if (tid >= o) t += y;
        }
        ws[tid] = t - orig;
    }
    __syncthreads();

    int run = s_boff + ws[wid] + wex;
#pragma unroll
    for (int i = 0; i < 4; i++) {
        int idx = base + i;
        if (idx < n) {
            g_rowptr[idx] = run;
            g_pos[idx] = run;
            g_dinv[idx] = rsqrtf((float)(a[i] + 1));
        }
        run += a[i];
    }
    if (blockIdx.x == 0 && tid == 0) g_rowptr[n] = E;
}

__global__ void scatter_kernel(const int* __restrict__ w, int E) {
    int e = blockIdx.x * blockDim.x + threadIdx.x;
    if (e >= E) return;
    int s, d;
    if (g_is64) { s = w[2 * e]; d = w[2 * (E + e)]; }
    else        { s = w[e];     d = w[E + e];       }
    float wn = g_dinv[s] * g_dinv[d];
    int p = atomicAdd(&g_pos[d], 1);
    g_edge[p] = make_int2(s, __float_as_int(wn));
}

// ---------------- register-tiled GEMM (proven round-3 version) ----------------
template<int KIN, int KOUT, int TN, bool INACT, bool OBIAS>
__global__ void __launch_bounds__((TN / 4) * 16)
gemm_rt(const float* __restrict__ A, const float* __restrict__ W,
        const float* __restrict__ ib, const float* __restrict__ ob,
        float* __restrict__ H, int n)
{
    constexpr int TM = 64;
    constexpr int TK = (KIN < 32) ? KIN : 32;
    constexpr int NTX = TN / 4;
    constexpr int NTH = NTX * 16;
    constexpr int XPITCH = TM + 4;

    __shared__ float Xs[TK * XPITCH];
    __shared__ float Ws[TK * TN];

    const int tid = threadIdx.x;
    const int tx = tid % NTX;
    const int ty = tid / NTX;
    const int nb = blockIdx.x * TM;
    const int jn = blockIdx.y * TN;
    const int valid = min(TM, n - nb);

    float acc[4][4];
#pragma unroll
    for (int i = 0; i < 4; i++)
#pragma unroll
        for (int j = 0; j < 4; j++) acc[i][j] = 0.0f;

    for (int kt = 0; kt < KIN; kt += TK) {
#pragma unroll
        for (int idx = tid; idx < TM * TK / 4; idx += NTH) {
            int r  = idx / (TK / 4);
            int kq = idx % (TK / 4);
            float4 v = make_float4(0.f, 0.f, 0.f, 0.f);
            if (r < valid)
                v = *reinterpret_cast<const float4*>(
                        A + (long long)(nb + r) * KIN + kt + kq * 4);
            if (INACT) {
                const float4 bb = *reinterpret_cast<const float4*>(ib + kt + kq * 4);
                v.x = fmaxf(v.x + bb.x, 0.f);
                v.y = fmaxf(v.y + bb.y, 0.f);
                v.z = fmaxf(v.z + bb.z, 0.f);
                v.w = fmaxf(v.w + bb.w, 0.f);
            }
            Xs[(kq * 4 + 0) * XPITCH + r] = v.x;
            Xs[(kq * 4 + 1) * XPITCH + r] = v.y;
            Xs[(kq * 4 + 2) * XPITCH + r] = v.z;
            Xs[(kq * 4 + 3) * XPITCH + r] = v.w;
        }
#pragma unroll
        for (int idx = tid; idx < TK * TN / 4; idx += NTH) {
            int kk = idx / (TN / 4);
            int jq = idx % (TN / 4);
            *reinterpret_cast<float4*>(Ws + kk * TN + jq * 4) =
                *reinterpret_cast<const float4*>(
                    W + (long long)(kt + kk) * KOUT + jn + jq * 4);
        }
        __syncthreads();

#pragma unroll
        for (int kk = 0; kk < TK; kk++) {
            const float4 a = *reinterpret_cast<const float4*>(Xs + kk * XPITCH + ty * 4);
            const float4 b = *reinterpret_cast<const float4*>(Ws + kk * TN + tx * 4);
            acc[0][0] += a.x * b.x; acc[0][1] += a.x * b.y; acc[0][2] += a.x * b.z; acc[0][3] += a.x * b.w;
            acc[1][0] += a.y * b.x; acc[1][1] += a.y * b.y; acc[1][2] += a.y * b.z; acc[1][3] += a.y * b.w;
            acc[2][0] += a.z * b.x; acc[2][1] += a.z * b.y; acc[2][2] += a.z * b.z; acc[2][3] += a.z * b.w;
            acc[3][0] += a.w * b.x; acc[3][1] += a.w * b.y; acc[3][2] += a.w * b.z; acc[3][3] += a.w * b.w;
        }
        __syncthreads();
    }

    float4 bo = make_float4(0.f, 0.f, 0.f, 0.f);
    if (OBIAS) bo = *reinterpret_cast<const float4*>(ob + jn + tx * 4);
#pragma unroll
    for (int i = 0; i < 4; i++) {
        int node = nb + ty * 4 + i;
        if (node < n) {
            float4 v = make_float4(acc[i][0] + bo.x, acc[i][1] + bo.y,
                                   acc[i][2] + bo.z, acc[i][3] + bo.w);
            *reinterpret_cast<float4*>(H + (long long)node * KOUT + jn + tx * 4) = v;
        }
    }
}

// ---------------- CSR gather propagation (8-edge pipelined) ----------------
// Branch-free tail: index clamped to r1-1, weight zeroed for phantom edges,
// so the final batch keeps full MLP instead of a serial scalar tail.
__global__ void __launch_bounds__(256)
prop64_kernel(const float* __restrict__ h, float* __restrict__ g, int n)
{
    const int v = (blockIdx.x * blockDim.x + threadIdx.x) >> 5;
    if (v >= n) return;
    const int lane = threadIdx.x & 31;
    const int r0 = g_rowptr[v];
    const int r1 = g_rowptr[v + 1];
    const float di = g_dinv[v];

    float2 acc = *reinterpret_cast<const float2*>(h + (long long)v * F1 + lane * 2);
    acc.x *= di * di;
    acc.y *= di * di;

    for (int j = r0; j < r1; j += 8) {
        int2 e[8];
        float wv[8];
#pragma unroll
        for (int i = 0; i < 8; i++) {
            int jj = (j + i < r1) ? (j + i) : (r1 - 1);
            e[i] = g_edge[jj];
            wv[i] = (j + i < r1) ? __int_as_float(e[i].y) : 0.0f;
        }
        float2 hv[8];
#pragma unroll
        for (int i = 0; i < 8; i++)
            hv[i] = *reinterpret_cast<const float2*>(h + (long long)e[i].x * F1 + lane * 2);
#pragma unroll
        for (int i = 0; i < 8; i++) {
            acc.x += wv[i] * hv[i].x;
            acc.y += wv[i] * hv[i].y;
        }
    }
    *reinterpret_cast<float2*>(g + (long long)v * F1 + lane * 2) = acc;
}

__global__ void __launch_bounds__(256)
prop32_kernel(const float* __restrict__ h, float* __restrict__ g, int n)
{
    const int v = (blockIdx.x * blockDim.x + threadIdx.x) >> 5;
    if (v >= n) return;
    const int lane = threadIdx.x & 31;
    const int r0 = g_rowptr[v];
    const int r1 = g_rowptr[v + 1];
    const float di = g_dinv[v];

    float acc = di * di * h[(long long)v * F2 + lane];

    for (int j = r0; j < r1; j += 8) {
        int2 e[8];
        float wv[8];
#pragma unroll
        for (int i = 0; i < 8; i++) {
            int jj = (j + i < r1) ? (j + i) : (r1 - 1);
            e[i] = g_edge[jj];
            wv[i] = (j + i < r1) ? __int_as_float(e[i].y) : 0.0f;
        }
        float hv[8];
#pragma unroll
        for (int i = 0; i < 8; i++)
            hv[i] = h[(long long)e[i].x * F2 + lane];
#pragma unroll
        for (int i = 0; i < 8; i++)
            acc += wv[i] * hv[i];
    }
    g[(long long)v * F2 + lane] = acc;
}

// ---------------- launcher (forked-stream capture) ----------------
extern "C" void kernel_launch(void* const* d_in, const int* in_sizes, int n_in,
                              void* d_out, int out_size)
{
    const float* x  = (const float*)d_in[0];
    const int*   ei = (const int*)  d_in[1];
    const float* W1 = (const float*)d_in[2];
    const float* b1 = (const float*)d_in[3];
    const float* W2 = (const float*)d_in[4];
    const float* b2 = (const float*)d_in[5];
    const float* Wl = (const float*)d_in[6];
    const float* bl = (const float*)d_in[7];
    float* out = (float*)d_out;

    const int n = in_sizes[0] / DIN;
    const int E = in_sizes[1] / 2;

    void *ph1, *pa1, *ph2, *pa2;
    cudaGetSymbolAddress(&ph1, g_h1);
    cudaGetSymbolAddress(&pa1, g_a1);
    cudaGetSymbolAddress(&ph2, g_h2);
    cudaGetSymbolAddress(&pa2, g_a2);
    float* h1 = (float*)ph1; float* a1 = (float*)pa1;
    float* h2 = (float*)ph2; float* a2 = (float*)pa2;

    const int nscan = (n + SCAN_ELEM - 1) / SCAN_ELEM;
    const int nblk = (n + 63) / 64;
    const int pblk = (n * 32 + 255) / 256;

    // side stream + fork/join events (host objects only; no device memory)
    cudaStream_t s2;
    cudaStreamCreateWithFlags(&s2, cudaStreamNonBlocking);
    cudaEvent_t evFork, evJoin;
    cudaEventCreateWithFlags(&evFork, cudaEventDisableTiming);
    cudaEventCreateWithFlags(&evJoin, cudaEventDisableTiming);

    // fork: CSR build on s2, concurrent with gemm1 on the main stream
    cudaEventRecord(evFork, 0);
    cudaStreamWaitEvent(s2, evFork, 0);

    detect_zero_kernel<<<(n + 255) / 256, 256, 0, s2>>>(ei, E, n);
    count_kernel<<<(E + 255) / 256, 256, 0, s2>>>(ei, E);
    scan1_kernel<<<nscan, 256, 0, s2>>>(n);
    scan3_kernel<<<nscan, 256, 0, s2>>>(n, E, nscan);
    scatter_kernel<<<(E + 255) / 256, 256, 0, s2>>>(ei, E);
    cudaEventRecord(evJoin, s2);

    // main stream: layer-1 GEMM overlaps CSR build
    gemm_rt<DIN, F1, 64, false, false><<<dim3(nblk, 1), 256>>>(x, W1, nullptr, nullptr, h1, n);

    // join: propagation needs both gemm1 and CSR
    cudaStreamWaitEvent(0, evJoin, 0);

    prop64_kernel<<<pblk, 256>>>(h1, a1, n);
    gemm_rt<F1, F2, 32, true, false><<<dim3(nblk, 1), 128>>>(a1, W2, b1, nullptr, h2, n);
    prop32_kernel<<<pblk, 256>>>(h2, a2, n);
    gemm_rt<F2, DOUT, 64, true, true><<<dim3(nblk, 2), 256>>>(a2, Wl, b2, bl, out, n);

    cudaEventDestroy(evFork);
    cudaEventDestroy(evJoin);
    cudaStreamDestroy(s2);
}